// round 14
// baseline (speedup 1.0000x reference)
#include <cuda_runtime.h>
#include <math.h>
#include <stdint.h>

#define NN 8192
#define DD 512
#define TEMP_INV 5.0f

// Scratch (device globals: no allocation allowed)
__device__ float  g_zn[(size_t)NN * DD];          // 16 MB normalized rows (tf32-rounded)
__device__ float  g_sim[(size_t)NN * NN];         // 256 MB Gram matrix
__device__ float2 g_colstat[NN];                  // per-column {sum, sumsq} of sim
__device__ float2 g_uA[NN];                       // {mean_sim_j, 1/(2*var_j)}
__device__ double g_neg;
__device__ double g_pos;

// ---------------------------------------------------------------------------
__global__ void init_kernel() {
    int j = blockIdx.x * blockDim.x + threadIdx.x;
    if (j < NN) g_colstat[j] = make_float2(0.f, 0.f);
    if (j == 0) { g_neg = 0.0; g_pos = 0.0; }
}

__global__ void nop_kernel() {}   // pads launch index so ncu (idx 3) captures the GEMM

__device__ __forceinline__ float tf32_rna(float x) {
    uint32_t u;
    asm("cvt.rna.tf32.f32 %0, %1;" : "=r"(u) : "f"(x));
    return __uint_as_float(u);
}

// ---------------------------------------------------------------------------
__global__ void normalize_kernel(const float* __restrict__ z) {
    int warp = (blockIdx.x * blockDim.x + threadIdx.x) >> 5;
    int lane = threadIdx.x & 31;
    if (warp >= NN) return;
    const float4* zr = (const float4*)(z + (size_t)warp * DD);
    float4 v[4];
    float ss = 0.f;
#pragma unroll
    for (int t = 0; t < 4; t++) {
        v[t] = zr[lane + 32 * t];
        ss += v[t].x * v[t].x + v[t].y * v[t].y + v[t].z * v[t].z + v[t].w * v[t].w;
    }
#pragma unroll
    for (int o = 16; o > 0; o >>= 1) ss += __shfl_xor_sync(0xffffffffu, ss, o);
    float inv = 1.0f / fmaxf(sqrtf(ss), 1e-12f);
    float4* outp = (float4*)(g_zn + (size_t)warp * DD);
#pragma unroll
    for (int t = 0; t < 4; t++) {
        float4 o4 = make_float4(tf32_rna(v[t].x * inv), tf32_rna(v[t].y * inv),
                                tf32_rna(v[t].z * inv), tf32_rna(v[t].w * inv));
        outp[lane + 32 * t] = o4;
    }
}

// ---------------------------------------------------------------------------
// TF32 mma.sync GEMM: 128x128 CTA, 4 warps (2x2), warp tile 64x64.
// B loaded in two nj-halves per k-slice (reduces live regs -> ptxas can
// software-pipeline at 2 warps/SMSP). Staging issued before MMAs.
#define SPITCH 36
#define STAGE_BYTES 36864     // 128*36*4 per matrix; A then B
#define GEMM_SMEM (3 * STAGE_BYTES)
#define TP 132                // epilogue tile pitch (words)

__device__ __forceinline__ void mma_tf32(float c[4], uint32_t a0, uint32_t a1,
                                         uint32_t a2, uint32_t a3,
                                         uint32_t b0, uint32_t b1) {
    asm volatile(
        "mma.sync.aligned.m16n8k8.row.col.f32.tf32.tf32.f32 "
        "{%0,%1,%2,%3}, {%4,%5,%6,%7}, {%8,%9}, {%0,%1,%2,%3};"
        : "+f"(c[0]), "+f"(c[1]), "+f"(c[2]), "+f"(c[3])
        : "r"(a0), "r"(a1), "r"(a2), "r"(a3), "r"(b0), "r"(b1));
}

__device__ __forceinline__ uint32_t smem_u32(const void* p) {
    uint32_t a;
    asm("{ .reg .u64 t; cvta.to.shared.u64 t, %1; cvt.u32.u64 %0, t; }" : "=r"(a) : "l"(p));
    return a;
}

__device__ __forceinline__ void stage_chunk_async(uint32_t sb, int buf, int br, int bc, int chunk) {
    uint32_t bA = sb + buf * STAGE_BYTES;
    uint32_t bB = bA + 18432;
    int t = threadIdx.x;
#pragma unroll
    for (int i = 0; i < 8; i++) {
        int idx = t + 128 * i;            // 0..1023
        int row = idx >> 3, q = idx & 7;
        uint32_t off = (uint32_t)(row * 144 + q * 16);   // 144 = SPITCH*4
        const float* ga = &g_zn[(size_t)(br * 128 + row) * DD + chunk * 32 + q * 4];
        const float* gb = &g_zn[(size_t)(bc * 128 + row) * DD + chunk * 32 + q * 4];
        asm volatile("cp.async.ca.shared.global [%0], [%1], 16;" :: "r"(bA + off), "l"(ga));
        asm volatile("cp.async.ca.shared.global [%0], [%1], 16;" :: "r"(bB + off), "l"(gb));
    }
}

__global__ void __launch_bounds__(128, 2) gemm_kernel() {
    // triangular block index -> (br, bc), br <= bc
    int lin = blockIdx.x;
    int br = (int)(64.5 - sqrt(64.5 * 64.5 - 2.0 * (double)lin));
    while (br * 64 - br * (br - 1) / 2 > lin) br--;
    while ((br + 1) * 64 - (br + 1) * br / 2 <= lin) br++;
    int bc = br + lin - (br * 64 - br * (br - 1) / 2);

    extern __shared__ char smem[];
    uint32_t sb = smem_u32(smem);

    int tid = threadIdx.x;
    int wid = tid >> 5, lane = tid & 31;
    int wm = wid >> 1, wn = wid & 1;     // 2x2 warp grid, warp tile 64x64
    int g = lane >> 2, c = lane & 3;

    float acc[4][8][4];
#pragma unroll
    for (int i = 0; i < 4; i++)
#pragma unroll
        for (int j = 0; j < 8; j++)
#pragma unroll
            for (int r = 0; r < 4; r++) acc[i][j][r] = 0.f;

    stage_chunk_async(sb, 0, br, bc, 0);
    asm volatile("cp.async.commit_group;");
    stage_chunk_async(sb, 1, br, bc, 1);
    asm volatile("cp.async.commit_group;");

    for (int ck = 0; ck < 16; ck++) {
        int buf = ck % 3;
        asm volatile("cp.async.wait_group 1;");
        __syncthreads();
        // issue next-next stage NOW so the copy overlaps this chunk's MMAs
        if (ck + 2 < 16) stage_chunk_async(sb, (ck + 2) % 3, br, bc, ck + 2);
        asm volatile("cp.async.commit_group;");   // empty group when no stage

        const float* fA = (const float*)(smem + buf * STAGE_BYTES) + (wm * 64 + g) * SPITCH;
        const float* fB = (const float*)(smem + buf * STAGE_BYTES + 18432) + (wn * 64 + g) * SPITCH;
#pragma unroll
        for (int ks = 0; ks < 4; ks++) {
            int k0 = ks * 8 + c;
            uint32_t a[4][4];
#pragma unroll
            for (int mi = 0; mi < 4; mi++) {
                a[mi][0] = __float_as_uint(fA[mi * 16 * SPITCH + k0]);
                a[mi][1] = __float_as_uint(fA[(mi * 16 + 8) * SPITCH + k0]);
                a[mi][2] = __float_as_uint(fA[mi * 16 * SPITCH + k0 + 4]);
                a[mi][3] = __float_as_uint(fA[(mi * 16 + 8) * SPITCH + k0 + 4]);
            }
#pragma unroll
            for (int h = 0; h < 2; h++) {
                uint32_t bf[4][2];
#pragma unroll
                for (int j = 0; j < 4; j++) {
                    int nj = 4 * h + j;
                    bf[j][0] = __float_as_uint(fB[nj * 8 * SPITCH + k0]);
                    bf[j][1] = __float_as_uint(fB[nj * 8 * SPITCH + k0 + 4]);
                }
#pragma unroll
                for (int mi = 0; mi < 4; mi++)
#pragma unroll
                    for (int j = 0; j < 4; j++)
                        mma_tf32(acc[mi][4 * h + j], a[mi][0], a[mi][1], a[mi][2], a[mi][3],
                                 bf[j][0], bf[j][1]);
            }
        }
    }
    asm volatile("cp.async.wait_group 0;");
    __syncthreads();   // staging buffers now free for epilogue reuse

    // ================= epilogue through smem =================
    float* tile = (float*)smem;                       // [128][TP]
    float* red  = (float*)(smem + 128 * TP * 4);      // [4][128]

    for (int t = tid; t < 512; t += 128) red[t] = 0.f;

    // acc -> tile (STS.64), plus register-based stats into red[]
    {
        int Rl = wm * 64 + g;
        int Cl = wn * 64 + 2 * c;
#pragma unroll
        for (int mi = 0; mi < 4; mi++) {
#pragma unroll
            for (int nj = 0; nj < 8; nj++) {
                int R0 = Rl + mi * 16, R1 = R0 + 8;
                int C = Cl + nj * 8;
                *(float2*)&tile[R0 * TP + C] = make_float2(acc[mi][nj][0], acc[mi][nj][1]);
                *(float2*)&tile[R1 * TP + C] = make_float2(acc[mi][nj][2], acc[mi][nj][3]);
            }
        }
    }
#pragma unroll
    for (int nj = 0; nj < 8; nj++) {
#pragma unroll
        for (int r2 = 0; r2 < 2; r2++) {
            float s = 0.f, q = 0.f;
#pragma unroll
            for (int mi = 0; mi < 4; mi++) {
                float x = acc[mi][nj][r2];     s += x; q = fmaf(x, x, q);
                float y = acc[mi][nj][r2 + 2]; s += y; q = fmaf(y, y, q);
            }
            int col = wn * 64 + nj * 8 + 2 * c + r2;
            atomicAdd(&red[col], s);
            atomicAdd(&red[128 + col], q);
        }
    }
    if (br != bc) {
#pragma unroll
        for (int mi = 0; mi < 4; mi++) {
#pragma unroll
            for (int h = 0; h < 2; h++) {
                float s = 0.f, q = 0.f;
#pragma unroll
                for (int nj = 0; nj < 8; nj++) {
                    float x = acc[mi][nj][2 * h];     s += x; q = fmaf(x, x, q);
                    float y = acc[mi][nj][2 * h + 1]; s += y; q = fmaf(y, y, q);
                }
                int row = wm * 64 + mi * 16 + 8 * h + g;
                atomicAdd(&red[256 + row], s);
                atomicAdd(&red[384 + row], q);
            }
        }
    }
    __syncthreads();

    // direct stores: warp wid owns rows wid*32..+31; LDS.128 + STG.128 coalesced
#pragma unroll
    for (int rr = 0; rr < 32; rr++) {
        int row = wid * 32 + rr;
        float4 v = *(float4*)&tile[row * TP + 4 * lane];
        *(float4*)&g_sim[(size_t)(br * 128 + row) * NN + bc * 128 + 4 * lane] = v;
    }
    // mirror stores: warp wid owns cols wid*32..+31; lane l reads rows l+32s
    if (br != bc) {
#pragma unroll
        for (int jj = 0; jj < 32; jj++) {
            int j = wid * 32 + jj;
            float* mrow = &g_sim[(size_t)(bc * 128 + j) * NN + br * 128];
#pragma unroll
            for (int s = 0; s < 4; s++) {
                int i = lane + 32 * s;
                mrow[i] = tile[i * TP + j];
            }
        }
    }
    // red -> global column stats (128 threads: cols first, then mirror rows)
    atomicAdd(&g_colstat[bc * 128 + tid].x, red[tid]);
    atomicAdd(&g_colstat[bc * 128 + tid].y, red[128 + tid]);
    if (br != bc) {
        atomicAdd(&g_colstat[br * 128 + tid].x, red[256 + tid]);
        atomicAdd(&g_colstat[br * 128 + tid].y, red[384 + tid]);
    }
}

// ---------------------------------------------------------------------------
__global__ void stats_fin_kernel() {
    int j = blockIdx.x * blockDim.x + threadIdx.x;
    if (j >= NN) return;
    float2 cs = g_colstat[j];
    double smean = (double)cs.x / (double)NN;
    double var = ((double)cs.y - (double)NN * smean * smean) / (double)(NN - 1);
    g_uA[j] = make_float2((float)smean, (float)(1.0 / (2.0 * var)));
}

// ---------------------------------------------------------------------------
__device__ __forceinline__ float neg_term(int lj, int li, float s, float u, float A) {
    float t = u - s;
    float e = fmaf(t * t, A, s * TEMP_INV);
    return (lj != li) ? __expf(e) : 0.f;
}

__global__ void __launch_bounds__(256) neg_kernel(const int* __restrict__ labels) {
    int i0 = blockIdx.x * 4;
    int li0 = __ldg(&labels[i0]);
    int li1 = __ldg(&labels[i0 + 1]);
    int li2 = __ldg(&labels[i0 + 2]);
    int li3 = __ldg(&labels[i0 + 3]);
    const float4* r0 = (const float4*)(g_sim + (size_t)i0 * NN);
    const float4* r1 = r0 + NN / 4;
    const float4* r2 = r1 + NN / 4;
    const float4* r3 = r2 + NN / 4;
    const int4* lab4 = (const int4*)labels;
    const float4* uA4 = (const float4*)g_uA;

    float acc = 0.f;
    for (int j4 = threadIdx.x; j4 < NN / 4; j4 += 256) {
        int4 L = __ldg(&lab4[j4]);
        float4 ua = __ldg(&uA4[2 * j4]);
        float4 ub = __ldg(&uA4[2 * j4 + 1]);
        float4 v0 = r0[j4];
        float4 v1 = r1[j4];
        float4 v2 = r2[j4];
        float4 v3 = r3[j4];

        acc += neg_term(L.x, li0, v0.x, ua.x, ua.y);
        acc += neg_term(L.y, li0, v0.y, ua.z, ua.w);
        acc += neg_term(L.z, li0, v0.z, ub.x, ub.y);
        acc += neg_term(L.w, li0, v0.w, ub.z, ub.w);

        acc += neg_term(L.x, li1, v1.x, ua.x, ua.y);
        acc += neg_term(L.y, li1, v1.y, ua.z, ua.w);
        acc += neg_term(L.z, li1, v1.z, ub.x, ub.y);
        acc += neg_term(L.w, li1, v1.w, ub.z, ub.w);

        acc += neg_term(L.x, li2, v2.x, ua.x, ua.y);
        acc += neg_term(L.y, li2, v2.y, ua.z, ua.w);
        acc += neg_term(L.z, li2, v2.z, ub.x, ub.y);
        acc += neg_term(L.w, li2, v2.w, ub.z, ub.w);

        acc += neg_term(L.x, li3, v3.x, ua.x, ua.y);
        acc += neg_term(L.y, li3, v3.y, ua.z, ua.w);
        acc += neg_term(L.z, li3, v3.z, ub.x, ub.y);
        acc += neg_term(L.w, li3, v3.w, ub.z, ub.w);
    }

    __shared__ double sh[256];
    int t = threadIdx.x;
    sh[t] = (double)acc;
    __syncthreads();
    for (int st = 128; st > 0; st >>= 1) {
        if (t < st) sh[t] += sh[t + st];
        __syncthreads();
    }
    if (t == 0) atomicAdd(&g_neg, sh[0]);
}

// ---------------------------------------------------------------------------
__global__ void pos_kernel(const int* __restrict__ labels) {
    int i = blockIdx.x * blockDim.x + threadIdx.x;
    double v = 0.0;
    const int b = NN / 2;
    if (i < b && labels[i] == labels[i + b]) {
        float s = g_sim[(size_t)i * NN + (i + b)];
        v = (double)expf(s * TEMP_INV);
    }
    __shared__ double sh[256];
    int t = threadIdx.x;
    sh[t] = v;
    __syncthreads();
    for (int st = 128; st > 0; st >>= 1) {
        if (t < st) sh[t] += sh[t + st];
        __syncthreads();
    }
    if (t == 0) atomicAdd(&g_pos, sh[0]);
}

// ---------------------------------------------------------------------------
__global__ void finalize_kernel(float* out) {
    out[0] = (float)(-log(g_pos / (g_pos + g_neg)));
}

// ---------------------------------------------------------------------------
extern "C" void kernel_launch(void* const* d_in, const int* in_sizes, int n_in,
                              void* d_out, int out_size) {
    const float* z      = (const float*)d_in[0];
    const int*   labels = (const int*)d_in[1];
    float*       out    = (float*)d_out;

    cudaFuncSetAttribute(gemm_kernel, cudaFuncAttributeMaxDynamicSharedMemorySize, GEMM_SMEM);

    init_kernel<<<NN / 256, 256>>>();        // idx 0
    normalize_kernel<<<NN / 8, 256>>>(z);    // idx 1
    nop_kernel<<<1, 1>>>();                  // idx 2
    gemm_kernel<<<2080, 128, GEMM_SMEM>>>(); // idx 3 (ncu capture target)
    stats_fin_kernel<<<NN / 256, 256>>>();   // idx 4
    neg_kernel<<<NN / 4, 256>>>(labels);     // idx 5
    pos_kernel<<<(NN / 2 + 255) / 256, 256>>>(labels);
    finalize_kernel<<<1, 1>>>(out);
}

// round 15
// speedup vs baseline: 1.0748x; 1.0748x over previous
#include <cuda_runtime.h>
#include <math.h>
#include <stdint.h>

#define NN 8192
#define DD 512
#define TEMP_INV 5.0f

// Scratch (device globals: no allocation allowed)
__device__ float  g_zn[(size_t)NN * DD];          // 16 MB normalized rows (tf32-rounded)
__device__ float  g_sim[(size_t)NN * NN];         // upper-triangle blocks only
__device__ float2 g_colstat[NN];                  // per-column {sum, sumsq} of sim
__device__ float2 g_uA[NN];                       // {mean_sim_j, 1/(2*var_j)}
__device__ double g_neg;
__device__ double g_pos;

// ---------------------------------------------------------------------------
__global__ void init_kernel() {
    int j = blockIdx.x * blockDim.x + threadIdx.x;
    if (j < NN) g_colstat[j] = make_float2(0.f, 0.f);
    if (j == 0) { g_neg = 0.0; g_pos = 0.0; }
}

__global__ void nop_kernel() {}   // pads launch index so ncu (idx 3) captures the GEMM

__device__ __forceinline__ float tf32_rna(float x) {
    uint32_t u;
    asm("cvt.rna.tf32.f32 %0, %1;" : "=r"(u) : "f"(x));
    return __uint_as_float(u);
}

// ---------------------------------------------------------------------------
__global__ void normalize_kernel(const float* __restrict__ z) {
    int warp = (blockIdx.x * blockDim.x + threadIdx.x) >> 5;
    int lane = threadIdx.x & 31;
    if (warp >= NN) return;
    const float4* zr = (const float4*)(z + (size_t)warp * DD);
    float4 v[4];
    float ss = 0.f;
#pragma unroll
    for (int t = 0; t < 4; t++) {
        v[t] = zr[lane + 32 * t];
        ss += v[t].x * v[t].x + v[t].y * v[t].y + v[t].z * v[t].z + v[t].w * v[t].w;
    }
#pragma unroll
    for (int o = 16; o > 0; o >>= 1) ss += __shfl_xor_sync(0xffffffffu, ss, o);
    float inv = 1.0f / fmaxf(sqrtf(ss), 1e-12f);
    float4* outp = (float4*)(g_zn + (size_t)warp * DD);
#pragma unroll
    for (int t = 0; t < 4; t++) {
        float4 o4 = make_float4(tf32_rna(v[t].x * inv), tf32_rna(v[t].y * inv),
                                tf32_rna(v[t].z * inv), tf32_rna(v[t].w * inv));
        outp[lane + 32 * t] = o4;
    }
}

// ---------------------------------------------------------------------------
// TF32 mma.sync GEMM (R11 config: 8 warps 2x4, warp tile 64x32), 3-stage
// cp.async pipeline, smem epilogue. UPPER-TRIANGLE ONLY: no mirror stores.
#define SPITCH 36
#define STAGE_BYTES 36864     // 128*36*4 per matrix; A then B
#define GEMM_SMEM (3 * STAGE_BYTES)
#define TP 132                // epilogue tile pitch (words)

__device__ __forceinline__ void mma_tf32(float c[4], uint32_t a0, uint32_t a1,
                                         uint32_t a2, uint32_t a3,
                                         uint32_t b0, uint32_t b1) {
    asm volatile(
        "mma.sync.aligned.m16n8k8.row.col.f32.tf32.tf32.f32 "
        "{%0,%1,%2,%3}, {%4,%5,%6,%7}, {%8,%9}, {%0,%1,%2,%3};"
        : "+f"(c[0]), "+f"(c[1]), "+f"(c[2]), "+f"(c[3])
        : "r"(a0), "r"(a1), "r"(a2), "r"(a3), "r"(b0), "r"(b1));
}

__device__ __forceinline__ uint32_t smem_u32(const void* p) {
    uint32_t a;
    asm("{ .reg .u64 t; cvta.to.shared.u64 t, %1; cvt.u32.u64 %0, t; }" : "=r"(a) : "l"(p));
    return a;
}

__device__ __forceinline__ void stage_chunk_async(uint32_t sb, int buf, int br, int bc, int chunk) {
    uint32_t bA = sb + buf * STAGE_BYTES;
    uint32_t bB = bA + 18432;
    int t = threadIdx.x;
#pragma unroll
    for (int i = 0; i < 4; i++) {
        int idx = t + 256 * i;            // 0..1023
        int row = idx >> 3, q = idx & 7;
        uint32_t off = (uint32_t)(row * 144 + q * 16);   // 144 = SPITCH*4
        const float* ga = &g_zn[(size_t)(br * 128 + row) * DD + chunk * 32 + q * 4];
        const float* gb = &g_zn[(size_t)(bc * 128 + row) * DD + chunk * 32 + q * 4];
        asm volatile("cp.async.ca.shared.global [%0], [%1], 16;" :: "r"(bA + off), "l"(ga));
        asm volatile("cp.async.ca.shared.global [%0], [%1], 16;" :: "r"(bB + off), "l"(gb));
    }
}

__global__ void __launch_bounds__(256, 2) gemm_kernel() {
    // triangular block index -> (br, bc), br <= bc
    int lin = blockIdx.x;
    int br = (int)(64.5 - sqrt(64.5 * 64.5 - 2.0 * (double)lin));
    while (br * 64 - br * (br - 1) / 2 > lin) br--;
    while ((br + 1) * 64 - (br + 1) * br / 2 <= lin) br++;
    int bc = br + lin - (br * 64 - br * (br - 1) / 2);

    extern __shared__ char smem[];
    uint32_t sb = smem_u32(smem);

    int tid = threadIdx.x;
    int wid = tid >> 5, lane = tid & 31;
    int wm = wid >> 2, wn = wid & 3;
    int g = lane >> 2, c = lane & 3;

    float acc[4][4][4];
#pragma unroll
    for (int i = 0; i < 4; i++)
#pragma unroll
        for (int j = 0; j < 4; j++)
#pragma unroll
            for (int r = 0; r < 4; r++) acc[i][j][r] = 0.f;

    stage_chunk_async(sb, 0, br, bc, 0);
    asm volatile("cp.async.commit_group;");
    stage_chunk_async(sb, 1, br, bc, 1);
    asm volatile("cp.async.commit_group;");

    for (int ck = 0; ck < 16; ck++) {
        int buf = ck % 3;
        asm volatile("cp.async.wait_group 1;");
        __syncthreads();

        const float* fA = (const float*)(smem + buf * STAGE_BYTES) + (wm * 64 + g) * SPITCH;
        const float* fB = (const float*)(smem + buf * STAGE_BYTES + 18432) + (wn * 32 + g) * SPITCH;
#pragma unroll
        for (int ks = 0; ks < 4; ks++) {
            int k0 = ks * 8 + c;
            uint32_t bf[4][2];
#pragma unroll
            for (int nj = 0; nj < 4; nj++) {
                bf[nj][0] = __float_as_uint(fB[nj * 8 * SPITCH + k0]);
                bf[nj][1] = __float_as_uint(fB[nj * 8 * SPITCH + k0 + 4]);
            }
#pragma unroll
            for (int mi = 0; mi < 4; mi++) {
                uint32_t a0 = __float_as_uint(fA[mi * 16 * SPITCH + k0]);
                uint32_t a1 = __float_as_uint(fA[(mi * 16 + 8) * SPITCH + k0]);
                uint32_t a2 = __float_as_uint(fA[mi * 16 * SPITCH + k0 + 4]);
                uint32_t a3 = __float_as_uint(fA[(mi * 16 + 8) * SPITCH + k0 + 4]);
#pragma unroll
                for (int nj = 0; nj < 4; nj++)
                    mma_tf32(acc[mi][nj], a0, a1, a2, a3, bf[nj][0], bf[nj][1]);
            }
        }
        if (ck + 2 < 16) stage_chunk_async(sb, (ck + 2) % 3, br, bc, ck + 2);
        asm volatile("cp.async.commit_group;");   // empty group when no stage: keeps counts
    }
    asm volatile("cp.async.wait_group 0;");
    __syncthreads();   // staging buffers now free for epilogue reuse

    // ================= epilogue through smem (direct tile only) =================
    float* tile = (float*)smem;                       // [128][TP]
    float* red  = (float*)(smem + 128 * TP * 4);      // [4][128]

    for (int t = tid; t < 512; t += 256) red[t] = 0.f;

    // acc -> tile (STS.64), plus register-based stats into red[]
    {
        int Rl = wm * 64 + g;
        int Cl = wn * 32 + 2 * c;
#pragma unroll
        for (int mi = 0; mi < 4; mi++) {
#pragma unroll
            for (int nj = 0; nj < 4; nj++) {
                int R0 = Rl + mi * 16, R1 = R0 + 8;
                int C = Cl + nj * 8;
                *(float2*)&tile[R0 * TP + C] = make_float2(acc[mi][nj][0], acc[mi][nj][1]);
                *(float2*)&tile[R1 * TP + C] = make_float2(acc[mi][nj][2], acc[mi][nj][3]);
            }
        }
    }
#pragma unroll
    for (int nj = 0; nj < 4; nj++) {
#pragma unroll
        for (int r2 = 0; r2 < 2; r2++) {
            float s = 0.f, q = 0.f;
#pragma unroll
            for (int mi = 0; mi < 4; mi++) {
                float x = acc[mi][nj][r2];     s += x; q = fmaf(x, x, q);
                float y = acc[mi][nj][r2 + 2]; s += y; q = fmaf(y, y, q);
            }
            int col = wn * 32 + nj * 8 + 2 * c + r2;
            atomicAdd(&red[col], s);
            atomicAdd(&red[128 + col], q);
        }
    }
    if (br != bc) {   // row sums feed the mirror columns' stats (no mirror stores)
#pragma unroll
        for (int mi = 0; mi < 4; mi++) {
#pragma unroll
            for (int h = 0; h < 2; h++) {
                float s = 0.f, q = 0.f;
#pragma unroll
                for (int nj = 0; nj < 4; nj++) {
                    float x = acc[mi][nj][2 * h];     s += x; q = fmaf(x, x, q);
                    float y = acc[mi][nj][2 * h + 1]; s += y; q = fmaf(y, y, q);
                }
                int row = wm * 64 + mi * 16 + 8 * h + g;
                atomicAdd(&red[256 + row], s);
                atomicAdd(&red[384 + row], q);
            }
        }
    }
    __syncthreads();

    // direct stores: warp wid owns rows wid*16..wid*16+15; LDS.128 + STG.128
#pragma unroll
    for (int rr = 0; rr < 16; rr++) {
        int row = wid * 16 + rr;
        float4 v = *(float4*)&tile[row * TP + 4 * lane];
        *(float4*)&g_sim[(size_t)(br * 128 + row) * NN + bc * 128 + 4 * lane] = v;
    }
    // red -> global column stats
    if (tid < 128) {
        atomicAdd(&g_colstat[bc * 128 + tid].x, red[tid]);
        atomicAdd(&g_colstat[bc * 128 + tid].y, red[128 + tid]);
    } else if (br != bc) {
        int r = tid - 128;
        atomicAdd(&g_colstat[br * 128 + r].x, red[256 + r]);
        atomicAdd(&g_colstat[br * 128 + r].y, red[384 + r]);
    }
}

// ---------------------------------------------------------------------------
__global__ void stats_fin_kernel() {
    int j = blockIdx.x * blockDim.x + threadIdx.x;
    if (j >= NN) return;
    float2 cs = g_colstat[j];
    double smean = (double)cs.x / (double)NN;
    double var = ((double)cs.y - (double)NN * smean * smean) / (double)(NN - 1);
    g_uA[j] = make_float2((float)smean, (float)(1.0 / (2.0 * var)));
}

// ---------------------------------------------------------------------------
// Negative sum over upper triangle only: each stored s_ij (i<j) contributes
// BOTH pair terms f_j(s)+f_i(s) when labels differ. Block b handles rows
// b and NN-1-b (combined length NN-1: balanced).
__global__ void __launch_bounds__(256) neg_kernel(const int* __restrict__ labels) {
    float acc = 0.f;
#pragma unroll
    for (int rr = 0; rr < 2; rr++) {
        int r = rr == 0 ? blockIdx.x : NN - 1 - blockIdx.x;
        int lr = __ldg(&labels[r]);
        float2 uAr = __ldg(&g_uA[r]);
        const float* row = g_sim + (size_t)r * NN;
        for (int j = r + 1 + threadIdx.x; j < NN; j += 256) {
            float s = row[j];
            int lj = __ldg(&labels[j]);
            if (lj != lr) {
                float2 uAj = __ldg(&g_uA[j]);
                float tj = uAj.x - s;
                float ti = uAr.x - s;
                acc += __expf(fmaf(tj * tj, uAj.y, s * TEMP_INV)) +
                       __expf(fmaf(ti * ti, uAr.y, s * TEMP_INV));
            }
        }
    }
    __shared__ double sh[256];
    int t = threadIdx.x;
    sh[t] = (double)acc;
    __syncthreads();
    for (int st = 128; st > 0; st >>= 1) {
        if (t < st) sh[t] += sh[t + st];
        __syncthreads();
    }
    if (t == 0) atomicAdd(&g_neg, sh[0]);
}

// ---------------------------------------------------------------------------
__global__ void pos_kernel(const int* __restrict__ labels) {
    int i = blockIdx.x * blockDim.x + threadIdx.x;
    double v = 0.0;
    const int b = NN / 2;
    if (i < b && labels[i] == labels[i + b]) {
        float s = g_sim[(size_t)i * NN + (i + b)];   // i < i+b: upper triangle
        v = (double)expf(s * TEMP_INV);
    }
    __shared__ double sh[256];
    int t = threadIdx.x;
    sh[t] = v;
    __syncthreads();
    for (int st = 128; st > 0; st >>= 1) {
        if (t < st) sh[t] += sh[t + st];
        __syncthreads();
    }
    if (t == 0) atomicAdd(&g_pos, sh[0]);
}

// ---------------------------------------------------------------------------
__global__ void finalize_kernel(float* out) {
    out[0] = (float)(-log(g_pos / (g_pos + g_neg)));
}

// ---------------------------------------------------------------------------
extern "C" void kernel_launch(void* const* d_in, const int* in_sizes, int n_in,
                              void* d_out, int out_size) {
    const float* z      = (const float*)d_in[0];
    const int*   labels = (const int*)d_in[1];
    float*       out    = (float*)d_out;

    cudaFuncSetAttribute(gemm_kernel, cudaFuncAttributeMaxDynamicSharedMemorySize, GEMM_SMEM);

    init_kernel<<<NN / 256, 256>>>();        // idx 0
    normalize_kernel<<<NN / 8, 256>>>(z);    // idx 1
    nop_kernel<<<1, 1>>>();                  // idx 2
    gemm_kernel<<<2080, 256, GEMM_SMEM>>>(); // idx 3 (ncu capture target)
    stats_fin_kernel<<<NN / 256, 256>>>();   // idx 4
    neg_kernel<<<NN / 2, 256>>>(labels);     // idx 5 (row-paired upper triangle)
    pos_kernel<<<(NN / 2 + 255) / 256, 256>>>(labels);
    finalize_kernel<<<1, 1>>>(out);
}